// round 4
// baseline (speedup 1.0000x reference)
#include <cuda_runtime.h>
#include <stdint.h>

#define IN_F   4096
#define OUT_F  4096
#define RANK_  16
#define MROWS  16384            // 4*4096 flattened rows
#define TH_    0xE6666600u      // bits < TH_  <=>  uniform(bits) < 0.9f (exact)
#define RB     16               // rows per block
#define KC     128              // k-chunk (phase A)
#define CBT    512              // col-chunk (phase B)

typedef unsigned long long u64;

// scratch (allocation-free rule: __device__ globals)
static __device__ float g_At[IN_F * RANK_];   // [k][r]  = A[r][k]
static __device__ float g_Bt[RANK_ * OUT_F];  // [r][o]  = B[o][r] * (scaling/keep)

// ---------- f32x2 helpers ----------
__device__ __forceinline__ u64 pack2f(float lo, float hi) {
    u64 r;
    asm("mov.b64 %0, {%1, %2};" : "=l"(r)
        : "r"(__float_as_uint(lo)), "r"(__float_as_uint(hi)));
    return r;
}
__device__ __forceinline__ void unpack2f(u64 v, float& lo, float& hi) {
    unsigned a, b;
    asm("mov.b64 {%0, %1}, %2;" : "=r"(a), "=r"(b) : "l"(v));
    lo = __uint_as_float(a); hi = __uint_as_float(b);
}
__device__ __forceinline__ u64 ffma2(u64 a, u64 b, u64 c) {
    u64 d;
    asm("fma.rn.f32x2 %0, %1, %2, %3;" : "=l"(d) : "l"(a), "l"(b), "l"(c));
    return d;
}
__device__ __forceinline__ u64 fadd2(u64 a, u64 b) {
    u64 d;
    asm("add.rn.f32x2 %0, %1, %2;" : "=l"(d) : "l"(a), "l"(b));
    return d;
}

// ---------- partitionable-threefry, two interleaved instances (ILP-2) ----------
// JAX (jax_threefry_partitionable=True): counter (0, i), key (0, 42),
// bits32 = o0 ^ o1 of a single threefry2x32-20.
__device__ __forceinline__ uint2 tf_bits2(unsigned ia, unsigned ib) {
    const unsigned ks1 = 42u, ks2 = 0x1BD11BF0u;  // 0x1BD11BDA ^ 0 ^ 42
    unsigned a0 = 0u, a1 = ia + ks1;
    unsigned b0 = 0u, b1 = ib + ks1;
#define R2(R) { a0 += a1; b0 += b1;                          \
                a1 = __funnelshift_l(a1, a1, (R));           \
                b1 = __funnelshift_l(b1, b1, (R));           \
                a1 ^= a0; b1 ^= b0; }
    R2(13) R2(15) R2(26) R2(6)
    a0 += ks1; b0 += ks1;   a1 += ks2 + 1u; b1 += ks2 + 1u;
    R2(17) R2(29) R2(16) R2(24)
    a0 += ks2; b0 += ks2;   a1 += 2u;       b1 += 2u;        // ks0 + 2
    R2(13) R2(15) R2(26) R2(6)
    /* += ks0(0) */         a1 += ks1 + 3u; b1 += ks1 + 3u;
    R2(17) R2(29) R2(16) R2(24)
    a0 += ks1; b0 += ks1;   a1 += ks2 + 4u; b1 += ks2 + 4u;
    R2(13) R2(15) R2(26) R2(6)
    a0 += ks2; b0 += ks2;   a1 += 5u;       b1 += 5u;        // ks0 + 5
#undef R2
    return make_uint2(a0 ^ a1, b0 ^ b1);
}

// ---------- k0: transpose A -> At, B*(2/0.9) -> Bt ----------
__global__ void k0_transpose(const float* __restrict__ A, const float* __restrict__ B) {
    const float CMUL = 2.0f / 0.9f;   // scaling / keep, folded into Bt
    int idx = blockIdx.x * blockDim.x + threadIdx.x;   // 0..4095
    if (idx < IN_F) {
#pragma unroll
        for (int r = 0; r < RANK_; ++r)
            g_At[idx * RANK_ + r] = A[r * IN_F + idx];
    }
    if (idx < OUT_F) {
#pragma unroll
        for (int r = 0; r < RANK_; ++r)
            g_Bt[r * OUT_F + idx] = B[idx * RANK_ + r] * CMUL;
    }
}

// ---------- fused kernel: T = x@A^T (phase A), y = dropout(T@Bt) (phase B) ----------
// 16 rows per block, 256 threads. smem: phase A region [0,16K) reused as B_s [0,32K),
// T_s lives at [32K, 34K).
__global__ void __launch_bounds__(256, 3) kf(const float* __restrict__ x,
                                             float* __restrict__ y) {
    __shared__ __align__(16) unsigned char sm[34816];
    float (*x_s)[KC]      = reinterpret_cast<float(*)[KC]>(sm);            //  8 KB
    u64   (*At_s2)[KC]    = reinterpret_cast<u64(*)[KC]>(sm + 8192);       //  8 KB
    u64   (*B_s)[CBT / 2] = reinterpret_cast<u64(*)[CBT / 2]>(sm);         // 32 KB (reuse)
    u64   (*T_s)[RANK_]   = reinterpret_cast<u64(*)[RANK_]>(sm + 32768);   //  2 KB

    const int tid   = threadIdx.x;
    const int wid   = tid >> 5;       // 0..7, warp owns rows {2w, 2w+1}
    const int lane  = tid & 31;
    const int rbase = blockIdx.x * RB;

    // ---------------- phase A: T[16][16] ----------------
    u64 acc2[2][8];
#pragma unroll
    for (int mi = 0; mi < 2; ++mi)
#pragma unroll
        for (int rr = 0; rr < 8; ++rr) acc2[mi][rr] = 0ull;

    for (int c = 0; c < IN_F / KC; ++c) {
        const float4* xg = reinterpret_cast<const float4*>(x + (size_t)rbase * IN_F + c * KC);
#pragma unroll
        for (int i = 0; i < 2; ++i) {
            int idx4 = tid + 256 * i;          // 0..511 float4s (16 x 32)
            int row  = idx4 >> 5;
            int col4 = idx4 & 31;
            float4 v = xg[(size_t)row * (IN_F / 4) + col4];
            *reinterpret_cast<float4*>(&x_s[row][col4 * 4]) = v;
        }
        if (tid < KC) {
            const float4* ag = reinterpret_cast<const float4*>(g_At + (size_t)(c * KC + tid) * RANK_);
            float4 a0 = ag[0], a1 = ag[1], a2v = ag[2], a3 = ag[3];
            At_s2[0][tid] = pack2f(a0.x,  a0.y);
            At_s2[1][tid] = pack2f(a0.z,  a0.w);
            At_s2[2][tid] = pack2f(a1.x,  a1.y);
            At_s2[3][tid] = pack2f(a1.z,  a1.w);
            At_s2[4][tid] = pack2f(a2v.x, a2v.y);
            At_s2[5][tid] = pack2f(a2v.z, a2v.w);
            At_s2[6][tid] = pack2f(a3.x,  a3.y);
            At_s2[7][tid] = pack2f(a3.z,  a3.w);
        }
        __syncthreads();

#pragma unroll
        for (int s = 0; s < KC / 32; ++s) {
            int k = lane + 32 * s;
            u64 a2[8];
#pragma unroll
            for (int rr = 0; rr < 8; ++rr) a2[rr] = At_s2[rr][k];
#pragma unroll
            for (int mi = 0; mi < 2; ++mi) {
                float xv = x_s[wid * 2 + mi][k];
                u64 xx = pack2f(xv, xv);
#pragma unroll
                for (int rr = 0; rr < 8; ++rr)
                    acc2[mi][rr] = ffma2(xx, a2[rr], acc2[mi][rr]);
            }
        }
        __syncthreads();
    }

    // butterfly reduce across 32 k-lanes
#pragma unroll
    for (int off = 16; off > 0; off >>= 1) {
#pragma unroll
        for (int mi = 0; mi < 2; ++mi)
#pragma unroll
            for (int rr = 0; rr < 8; ++rr) {
                u64 o = __shfl_xor_sync(0xffffffffu, acc2[mi][rr], off);
                acc2[mi][rr] = fadd2(acc2[mi][rr], o);
            }
    }
    if (lane < RANK_) {
#pragma unroll
        for (int mi = 0; mi < 2; ++mi) {
            float lo, hi;
            unpack2f(acc2[mi][lane >> 1], lo, hi);
            float v = (lane & 1) ? hi : lo;
            T_s[wid * 2 + mi][lane] = pack2f(v, v);
        }
    }
    __syncthreads();

    // ---------------- phase B: y = dropout(T @ Bt) ----------------
#pragma unroll 1
    for (int cc = 0; cc < OUT_F / CBT; ++cc) {
        const int cb = cc * CBT;
        // stage Bt slice 16 x 512 (coalesced float4 -> u64 pairs)
#pragma unroll
        for (int i = 0; i < 8; ++i) {
            int idx4 = tid + 256 * i;          // 0..2047 float4s
            int r    = idx4 >> 7;              // 128 float4 per row
            int c4   = idx4 & 127;
            float4 v = *reinterpret_cast<const float4*>(&g_Bt[r * OUT_F + cb + c4 * 4]);
            B_s[r][c4 * 2]     = pack2f(v.x, v.y);
            B_s[r][c4 * 2 + 1] = pack2f(v.z, v.w);
        }
        __syncthreads();

        u64 b[RANK_];
#pragma unroll
        for (int r = 0; r < RANK_; ++r) b[r] = B_s[r][tid];

#pragma unroll 1
        for (int q = 0; q < RB; ++q) {
            u64 acc = 0ull;
#pragma unroll
            for (int rp = 0; rp < RANK_ / 2; ++rp) {
                ulonglong2 t2 = *reinterpret_cast<const ulonglong2*>(&T_s[q][rp * 2]);
                acc = ffma2(t2.x, b[rp * 2],     acc);
                acc = ffma2(t2.y, b[rp * 2 + 1], acc);
            }
            float v0, v1;
            unpack2f(acc, v0, v1);

            const int m = rbase + q;
            unsigned base_i = (unsigned)m * 4096u + (unsigned)(cb + tid * 2);
            uint2 bb = tf_bits2(base_i, base_i + 1u);
            float o0 = (bb.x < TH_) ? v0 : 0.0f;
            float o1 = (bb.y < TH_) ? v1 : 0.0f;
            *reinterpret_cast<float2*>(&y[(size_t)m * 4096 + cb + tid * 2]) =
                make_float2(o0, o1);
        }
        __syncthreads();
    }
}

extern "C" void kernel_launch(void* const* d_in, const int* in_sizes, int n_in,
                              void* d_out, int out_size) {
    const float* x = (const float*)d_in[0];
    const float* A = (const float*)d_in[1];
    const float* B = (const float*)d_in[2];
    float*       y = (float*)d_out;

    k0_transpose<<<16, 256>>>(A, B);
    kf<<<MROWS / RB, 256>>>(x, y);
}

// round 5
// speedup vs baseline: 1.0732x; 1.0732x over previous
#include <cuda_runtime.h>
#include <stdint.h>

#define IN_F   4096
#define OUT_F  4096
#define RANK_  16
#define MROWS  16384            // 4*4096 flattened rows
#define TH_    0xE6666600u      // bits < TH_  <=>  uniform(bits) < 0.9f (exact)
#define KC     128              // k-chunk (k1)
#define BM1    16               // rows per block (k1)
#define RB     16               // rows per block (k2)
#define CBT    512              // col-chunk (k2)

typedef unsigned long long u64;

// scratch (allocation-free rule: __device__ globals)
static __device__ float g_At[IN_F * RANK_];   // [k][r]  = A[r][k]
static __device__ float g_Bt[RANK_ * OUT_F];  // [r][o]  = B[o][r] * (scaling/keep)
static __device__ u64   g_T2[MROWS * RANK_];  // T packed as (v,v) f32x2

// ---------- f32x2 helpers ----------
__device__ __forceinline__ u64 pack2f(float lo, float hi) {
    u64 r;
    asm("mov.b64 %0, {%1, %2};" : "=l"(r)
        : "r"(__float_as_uint(lo)), "r"(__float_as_uint(hi)));
    return r;
}
__device__ __forceinline__ void unpack2f(u64 v, float& lo, float& hi) {
    unsigned a, b;
    asm("mov.b64 {%0, %1}, %2;" : "=r"(a), "=r"(b) : "l"(v));
    lo = __uint_as_float(a); hi = __uint_as_float(b);
}
__device__ __forceinline__ u64 ffma2(u64 a, u64 b, u64 c) {
    u64 d;
    asm("fma.rn.f32x2 %0, %1, %2, %3;" : "=l"(d) : "l"(a), "l"(b), "l"(c));
    return d;
}
__device__ __forceinline__ u64 fadd2(u64 a, u64 b) {
    u64 d;
    asm("add.rn.f32x2 %0, %1, %2;" : "=l"(d) : "l"(a), "l"(b));
    return d;
}

// ---------- partitionable-threefry, four interleaved instances (ILP-4) ----------
// JAX (jax_threefry_partitionable=True): counter (0, i), key (0, 42),
// bits32 = o0 ^ o1 of a single threefry2x32-20.
__device__ __forceinline__ void tf_bits4(unsigned i0, unsigned i1,
                                         unsigned i2, unsigned i3,
                                         unsigned out[4]) {
    const unsigned ks1 = 42u, ks2 = 0x1BD11BF0u;  // 0x1BD11BDA ^ 0 ^ 42
    unsigned x0[4], x1[4];
    x0[0] = x0[1] = x0[2] = x0[3] = 0u;
    x1[0] = i0 + ks1; x1[1] = i1 + ks1; x1[2] = i2 + ks1; x1[3] = i3 + ks1;
#define R4(R) { _Pragma("unroll") for (int j = 0; j < 4; ++j) {            \
                    x0[j] += x1[j];                                        \
                    x1[j] = __funnelshift_l(x1[j], x1[j], (R));            \
                    x1[j] ^= x0[j]; } }
#define KADD(C0, C1) { _Pragma("unroll") for (int j = 0; j < 4; ++j) {     \
                           x0[j] += (C0); x1[j] += (C1); } }
    R4(13) R4(15) R4(26) R4(6)
    KADD(ks1, ks2 + 1u)
    R4(17) R4(29) R4(16) R4(24)
    KADD(ks2, 2u)                 // ks0 + 2
    R4(13) R4(15) R4(26) R4(6)
    KADD(0u, ks1 + 3u)            // ks0 elided on x0
    R4(17) R4(29) R4(16) R4(24)
    KADD(ks1, ks2 + 4u)
    R4(13) R4(15) R4(26) R4(6)
    KADD(ks2, 5u)                 // ks0 + 5
#undef R4
#undef KADD
#pragma unroll
    for (int j = 0; j < 4; ++j) out[j] = x0[j] ^ x1[j];
}

// ---------- k0: transpose A -> At, B*(2/0.9) -> Bt ----------
__global__ void k0_transpose(const float* __restrict__ A, const float* __restrict__ B) {
    const float CMUL = 2.0f / 0.9f;   // scaling / keep, folded into Bt
    int idx = blockIdx.x * blockDim.x + threadIdx.x;   // 0..4095
    if (idx < IN_F) {
#pragma unroll
        for (int r = 0; r < RANK_; ++r)
            g_At[idx * RANK_ + r] = A[r * IN_F + idx];
    }
    if (idx < OUT_F) {
#pragma unroll
        for (int r = 0; r < RANK_; ++r)
            g_Bt[r * OUT_F + idx] = B[idx * RANK_ + r] * CMUL;
    }
}

// ---------- k1: T = x @ A^T ----------
// 256 threads (8 warps), 16 rows/block, 2 rows/warp -> 16 u64 accumulators.
__global__ void __launch_bounds__(256, 3) k1_xa(const float* __restrict__ x) {
    __shared__ float x_s[BM1][KC];          // 8 KB
    __shared__ u64   At_s2[RANK_ / 2][KC];  // 8 KB

    const int tid  = threadIdx.x;
    const int wid  = tid >> 5;   // 0..7, warp owns rows {2w, 2w+1}
    const int lane = tid & 31;
    const int m0   = blockIdx.x * BM1;

    u64 acc2[2][8];
#pragma unroll
    for (int mi = 0; mi < 2; ++mi)
#pragma unroll
        for (int rr = 0; rr < 8; ++rr) acc2[mi][rr] = 0ull;

    for (int c = 0; c < IN_F / KC; ++c) {
        const float4* xg = reinterpret_cast<const float4*>(x + (size_t)m0 * IN_F + c * KC);
#pragma unroll
        for (int i = 0; i < 2; ++i) {
            int idx4 = tid + 256 * i;          // 0..511 float4s (16 x 32)
            int row  = idx4 >> 5;
            int col4 = idx4 & 31;
            float4 v = xg[(size_t)row * (IN_F / 4) + col4];
            *reinterpret_cast<float4*>(&x_s[row][col4 * 4]) = v;
        }
        if (tid < KC) {
            const float4* ag = reinterpret_cast<const float4*>(g_At + (size_t)(c * KC + tid) * RANK_);
            float4 a0 = ag[0], a1 = ag[1], a2v = ag[2], a3 = ag[3];
            At_s2[0][tid] = pack2f(a0.x,  a0.y);
            At_s2[1][tid] = pack2f(a0.z,  a0.w);
            At_s2[2][tid] = pack2f(a1.x,  a1.y);
            At_s2[3][tid] = pack2f(a1.z,  a1.w);
            At_s2[4][tid] = pack2f(a2v.x, a2v.y);
            At_s2[5][tid] = pack2f(a2v.z, a2v.w);
            At_s2[6][tid] = pack2f(a3.x,  a3.y);
            At_s2[7][tid] = pack2f(a3.z,  a3.w);
        }
        __syncthreads();

#pragma unroll
        for (int s = 0; s < KC / 32; ++s) {
            int k = lane + 32 * s;
            u64 a2[8];
#pragma unroll
            for (int rr = 0; rr < 8; ++rr) a2[rr] = At_s2[rr][k];
#pragma unroll
            for (int mi = 0; mi < 2; ++mi) {
                float xv = x_s[wid * 2 + mi][k];
                u64 xx = pack2f(xv, xv);
#pragma unroll
                for (int rr = 0; rr < 8; ++rr)
                    acc2[mi][rr] = ffma2(xx, a2[rr], acc2[mi][rr]);
            }
        }
        __syncthreads();
    }

    // butterfly reduce across 32 k-lanes
#pragma unroll
    for (int off = 16; off > 0; off >>= 1) {
#pragma unroll
        for (int mi = 0; mi < 2; ++mi)
#pragma unroll
            for (int rr = 0; rr < 8; ++rr) {
                u64 o = __shfl_xor_sync(0xffffffffu, acc2[mi][rr], off);
                acc2[mi][rr] = fadd2(acc2[mi][rr], o);
            }
    }
    if (lane < RANK_) {
#pragma unroll
        for (int mi = 0; mi < 2; ++mi) {
            float lo, hi;
            unpack2f(acc2[mi][lane >> 1], lo, hi);
            float v = (lane & 1) ? hi : lo;
            g_T2[(size_t)(m0 + wid * 2 + mi) * RANK_ + lane] = pack2f(v, v);
        }
    }
}

// ---------- k2: y = dropout( T @ Bt ), 2 rows/iter, ILP-4 threefry ----------
__global__ void __launch_bounds__(256, 3) k2_by(float* __restrict__ y) {
    __shared__ u64 B_s[RANK_][CBT / 2];  // 32 KB, col pairs
    __shared__ u64 T_s[RB][RANK_];       // 2 KB, (t,t) packed

    const int tid   = threadIdx.x;
    const int cb    = (blockIdx.x & 7) * CBT;           // col tile 0..7
    const int rbase = (blockIdx.x >> 3) * RB;           // row tile

    // stage Bt slice: 16 x 512 floats, coalesced float4
#pragma unroll
    for (int i = 0; i < 8; ++i) {
        int idx4 = tid + 256 * i;          // 0..2047 float4s
        int r    = idx4 >> 7;              // 128 float4 per row
        int c4   = idx4 & 127;
        float4 v = *reinterpret_cast<const float4*>(&g_Bt[r * OUT_F + cb + c4 * 4]);
        B_s[r][c4 * 2]     = pack2f(v.x, v.y);
        B_s[r][c4 * 2 + 1] = pack2f(v.z, v.w);
    }
    // stage T rows (already packed (v,v) by k1)
    {
        int row = tid >> 4;                // 0..15
        int r   = tid & 15;
        T_s[row][r] = g_T2[(size_t)(rbase + row) * RANK_ + r];
    }
    __syncthreads();

    // this thread's B column-pair, held across all rows
    u64 b[RANK_];
#pragma unroll
    for (int r = 0; r < RANK_; ++r) b[r] = B_s[r][tid];

#pragma unroll 1
    for (int q = 0; q < RB; q += 2) {
        u64 accA = 0ull, accB = 0ull;
#pragma unroll
        for (int rp = 0; rp < RANK_ / 2; ++rp) {
            ulonglong2 tA = *reinterpret_cast<const ulonglong2*>(&T_s[q][rp * 2]);
            ulonglong2 tB = *reinterpret_cast<const ulonglong2*>(&T_s[q + 1][rp * 2]);
            accA = ffma2(tA.x, b[rp * 2],     accA);
            accA = ffma2(tA.y, b[rp * 2 + 1], accA);
            accB = ffma2(tB.x, b[rp * 2],     accB);
            accB = ffma2(tB.y, b[rp * 2 + 1], accB);
        }
        float a0, a1, b0, b1;
        unpack2f(accA, a0, a1);
        unpack2f(accB, b0, b1);

        const int m = rbase + q;
        unsigned base_i = (unsigned)m * 4096u + (unsigned)(cb + tid * 2);
        unsigned bits[4];
        tf_bits4(base_i, base_i + 1u, base_i + 4096u, base_i + 4097u, bits);
        float o0 = (bits[0] < TH_) ? a0 : 0.0f;
        float o1 = (bits[1] < TH_) ? a1 : 0.0f;
        float o2 = (bits[2] < TH_) ? b0 : 0.0f;
        float o3 = (bits[3] < TH_) ? b1 : 0.0f;
        *reinterpret_cast<float2*>(&y[(size_t)m * 4096 + cb + tid * 2]) =
            make_float2(o0, o1);
        *reinterpret_cast<float2*>(&y[(size_t)(m + 1) * 4096 + cb + tid * 2]) =
            make_float2(o2, o3);
    }
}

extern "C" void kernel_launch(void* const* d_in, const int* in_sizes, int n_in,
                              void* d_out, int out_size) {
    const float* x = (const float*)d_in[0];
    const float* A = (const float*)d_in[1];
    const float* B = (const float*)d_in[2];
    float*       y = (float*)d_out;

    k0_transpose<<<16, 256>>>(A, B);
    k1_xa<<<MROWS / BM1, 256>>>(x);
    k2_by<<<(MROWS / RB) * (OUT_F / CBT), 256>>>(y);
}